// round 4
// baseline (speedup 1.0000x reference)
#include <cuda_runtime.h>
#include <cuda_bf16.h>
#include <math.h>

#define NPIX   768
#define NP     (NPIX * NPIX)       // 589824
#define NP4    (NP / 4)            // 147456
#define NTERMS 128
#define PPSZ   256
#define NOUT   (PPSZ * PPSZ)       // 65536

// Scratch for latent^T: L[I][J] = sum_n basis[n, I, J] * coeffs[n]  (2.36 MB)
__device__ float g_latent[NP];

// ---------------------------------------------------------------------------
// Kernel 1: HBM-streaming weighted reduction over the 128 basis terms.
// Thread t owns float4-pixel index t; reads basis[n*NP4 + t] for n=0..127.
// Fully coalesced 128-bit loads, unroll 8 for MLP.
// ---------------------------------------------------------------------------
__global__ void __launch_bounds__(256) latent_kernel(
    const float4* __restrict__ basis4,
    const float*  __restrict__ coeffs)
{
    __shared__ float sc[NTERMS];
    if (threadIdx.x < NTERMS) sc[threadIdx.x] = coeffs[threadIdx.x];
    __syncthreads();

    int idx = blockIdx.x * blockDim.x + threadIdx.x;   // 0 .. NP4-1
    if (idx >= NP4) return;

    const float4* p = basis4 + idx;
    float4 acc = make_float4(0.f, 0.f, 0.f, 0.f);

#pragma unroll 8
    for (int n = 0; n < NTERMS; n++) {
        float4 v = p[(size_t)n * NP4];
        float  c = sc[n];
        acc.x = fmaf(v.x, c, acc.x);
        acc.y = fmaf(v.y, c, acc.y);
        acc.z = fmaf(v.z, c, acc.z);
        acc.w = fmaf(v.w, c, acc.w);
    }
    reinterpret_cast<float4*>(g_latent)[idx] = acc;
}

// ---------------------------------------------------------------------------
// Kernel 2: CLIMB area per 3x3 patch.
// out[Cb*256 + Rb] from z[3r+c] = L[(3Cb+c)*768 + 3Rb+r]
// ---------------------------------------------------------------------------
__global__ void __launch_bounds__(256) climb_kernel(
    float* __restrict__ out,
    const float* __restrict__ wavel_ptr)
{
    int o = blockIdx.x * blockDim.x + threadIdx.x;
    if (o >= NOUT) return;
    int Cb = o >> 8;
    int Rb = o & 255;

    float z[9];
#pragma unroll
    for (int c = 0; c < 3; c++) {
        int I = 3 * Cb + c;
#pragma unroll
        for (int r = 0; r < 3; r++) {
            z[3 * r + c] = g_latent[I * NPIX + (3 * Rb + r)];
        }
    }

    // Least-squares plane fit over unit 3x3 grid (x = c/2, y = r/2).
    // Regressors (x-1/2), (y-1/2), 1 are mutually orthogonal over the grid:
    //   a = sum z*(x-1/2) / 1.5 ,  b = sum z*(y-1/2) / 1.5 ,
    //   c = mean(z) - a/2 - b/2
    float S = 0.f, Sx = 0.f, Sy = 0.f;
    bool allpos = true, allnonpos = true, anyzero = false;
#pragma unroll
    for (int k = 0; k < 9; k++) {
        float v  = z[k];
        float xk = 0.5f * (float)(k % 3);
        float yk = 0.5f * (float)(k / 3);
        S  += v;
        Sx += v * xk;
        Sy += v * yk;
        allpos    = allpos    && (v > 0.f);
        allnonpos = allnonpos && (v <= 0.f);
        anyzero   = anyzero   || (v == 0.f);
    }
    float mean = S * (1.f / 9.f);
    float a = (Sx - 0.5f * S) * (1.f / 1.5f);
    float b = (Sy - 0.5f * S) * (1.f / 1.5f);
    float c = mean - 0.5f * a - 0.5f * b;

    const float EPSF = 1e-15f;
    if (a == 0.f) a = EPSF;
    if (b == 0.f) b = EPSF;
    if (c == 0.f) c = EPSF;

    float x1 = (-b - c) / a;
    float x2 = (-c) / a;
    float lo = fminf(x1, x2);
    float hi = fmaxf(x1, x2);
    x1 = fmaxf(lo, 0.f);
    x2 = fminf(hi, 1.f);

    float ncb = (-c) / b;          // -c/b
    float ab  = a / b;             // a/b
    float d = x1 + ncb * x2 - 0.5f * ab * x2 * x2
                 - ncb * x1 + 0.5f * ab * x1 * x1;

    d = (d >= 0.5f) ? d : (1.0f - d);
    d = (mean >= 0.f) ? d : (1.0f - d);
    if (allpos)    d = 1.0f;
    if (allnonpos) d = 0.0f;
    if (anyzero)   d = (d > 0.f) ? 1.0f : 0.0f;
    d = fminf(fmaxf(d, 0.f), 1.f);

    // opd = (pi * d) * wavel / (2*pi) = 0.5 * d * wavel
    float wl = *wavel_ptr;
    out[o] = ((float)M_PI * d) * wl * (1.0f / (2.0f * (float)M_PI));
}

extern "C" void kernel_launch(void* const* d_in, const int* in_sizes, int n_in,
                              void* d_out, int out_size)
{
    const float4* basis4 = reinterpret_cast<const float4*>(d_in[0]); // (128,768,768) f32
    const float*  coeffs = reinterpret_cast<const float*>(d_in[1]);  // (128,)
    const float*  wavel  = reinterpret_cast<const float*>(d_in[2]);  // scalar
    float*        out    = reinterpret_cast<float*>(d_out);          // (256,256) f32

    (void)in_sizes; (void)n_in; (void)out_size;

    latent_kernel<<<(NP4 + 255) / 256, 256>>>(basis4, coeffs);
    climb_kernel<<<(NOUT + 255) / 256, 256>>>(out, wavel);
}